// round 2
// baseline (speedup 1.0000x reference)
#include <cuda_runtime.h>
#include <math.h>

#define ED 1024
#define HD 128
#define BATCH 4
#define SEQ 2048
#define BM 64
#define BN 64
#define NTHREADS 256

// Scratch for projected Q, K, V  (4 MB each)
__device__ float g_q[BATCH * SEQ * HD];
__device__ float g_k[BATCH * SEQ * HD];
__device__ float g_v[BATCH * SEQ * HD];

// ---------------------------------------------------------------------------
// Kernel 1: fused QKV projection.  C[64][128] = X[64][1024] @ W[1024][128] + b
// blockIdx.x = row tile (8192/64 = 128), blockIdx.y = which of {q,k,v}
// ---------------------------------------------------------------------------
__global__ __launch_bounds__(NTHREADS) void qkv_proj_kernel(
    const float* __restrict__ x,
    const float* __restrict__ wq, const float* __restrict__ bq,
    const float* __restrict__ wk, const float* __restrict__ bk,
    const float* __restrict__ wv, const float* __restrict__ bv)
{
    const float* w;
    const float* bias;
    float* out;
    switch (blockIdx.y) {
        case 0:  w = wq; bias = bq; out = g_q; break;
        case 1:  w = wk; bias = bk; out = g_k; break;
        default: w = wv; bias = bv; out = g_v; break;
    }

    __shared__ float sX[32 * 64];    // [kk][r]  (transposed X tile)
    __shared__ float sW[32 * 128];   // [kk][c]

    const int tid  = threadIdx.x;
    const int row0 = blockIdx.x * 64;
    const int r0   = (tid / 32) * 8;   // 8 output rows per thread
    const int c0   = (tid % 32) * 4;   // 4 output cols per thread

    float acc[8][4];
#pragma unroll
    for (int i = 0; i < 8; i++)
#pragma unroll
        for (int j = 0; j < 4; j++) acc[i][j] = 0.0f;

    for (int kt = 0; kt < ED; kt += 32) {
        __syncthreads();
        // Load X tile 64x32, store transposed [kk][r]
#pragma unroll
        for (int s = 0; s < 2; s++) {
            int f   = tid + s * NTHREADS;       // 512 float4 total
            int r   = f / 8;                    // 8 float4 per row
            int kk0 = (f % 8) * 4;
            float4 v4 = *reinterpret_cast<const float4*>(
                &x[(size_t)(row0 + r) * ED + kt + kk0]);
            sX[(kk0 + 0) * 64 + r] = v4.x;
            sX[(kk0 + 1) * 64 + r] = v4.y;
            sX[(kk0 + 2) * 64 + r] = v4.z;
            sX[(kk0 + 3) * 64 + r] = v4.w;
        }
        // Load W tile 32x128, direct copy [kk][c]
#pragma unroll
        for (int s = 0; s < 4; s++) {
            int f   = tid + s * NTHREADS;       // 1024 float4 total
            int kk  = f / 32;
            int cc  = (f % 32) * 4;
            *reinterpret_cast<float4*>(&sW[kk * 128 + cc]) =
                *reinterpret_cast<const float4*>(&w[(size_t)(kt + kk) * HD + cc]);
        }
        __syncthreads();

#pragma unroll
        for (int kk = 0; kk < 32; kk++) {
            float4 xa = *reinterpret_cast<float4*>(&sX[kk * 64 + r0]);
            float4 xb = *reinterpret_cast<float4*>(&sX[kk * 64 + r0 + 4]);
            float4 wv4 = *reinterpret_cast<float4*>(&sW[kk * 128 + c0]);
            float xr[8] = {xa.x, xa.y, xa.z, xa.w, xb.x, xb.y, xb.z, xb.w};
            float wr[4] = {wv4.x, wv4.y, wv4.z, wv4.w};
#pragma unroll
            for (int i = 0; i < 8; i++)
#pragma unroll
                for (int j = 0; j < 4; j++)
                    acc[i][j] = fmaf(xr[i], wr[j], acc[i][j]);
        }
    }

    // bias + store
#pragma unroll
    for (int i = 0; i < 8; i++) {
        float4 o;
        o.x = acc[i][0] + bias[c0 + 0];
        o.y = acc[i][1] + bias[c0 + 1];
        o.z = acc[i][2] + bias[c0 + 2];
        o.w = acc[i][3] + bias[c0 + 3];
        *reinterpret_cast<float4*>(&out[(size_t)(row0 + r0 + i) * HD + c0]) = o;
    }
}

// ---------------------------------------------------------------------------
// Kernel 2: causal flash attention, BM=BN=64, D=128.
// blockIdx.x = query tile (32), blockIdx.y = batch (4)
// ---------------------------------------------------------------------------
__global__ __launch_bounds__(NTHREADS) void attn_kernel(float* __restrict__ out)
{
    extern __shared__ float sm[];
    float* sQt = sm;                 // [d][r]  128*64
    float* sKt = sQt + 128 * 64;     // [d][c]  128*64
    float* sV  = sKt + 128 * 64;     // [j][d]  64*128
    float* sP  = sV  + 64 * 128;     // [r][j]  stride 65
    float* sM  = sP  + 64 * 65;
    float* sL  = sM  + 64;
    float* sC  = sL  + 64;

    const int tid = threadIdx.x;
    const int b   = blockIdx.y;
    const int qt  = blockIdx.x;
    const int q0  = qt * BM;

    const float* Q = g_q + (size_t)b * SEQ * HD;
    const float* K = g_k + (size_t)b * SEQ * HD;
    const float* V = g_v + (size_t)b * SEQ * HD;

    const float scale = 0.08838834764831845f;  // 1/sqrt(128)

    // Load Q tile transposed
#pragma unroll
    for (int s = 0; s < 8; s++) {
        int f  = tid + s * NTHREADS;   // 2048 float4
        int r  = f / 32;
        int d0 = (f % 32) * 4;
        float4 v4 = *reinterpret_cast<const float4*>(&Q[(size_t)(q0 + r) * HD + d0]);
        sQt[(d0 + 0) * 64 + r] = v4.x;
        sQt[(d0 + 1) * 64 + r] = v4.y;
        sQt[(d0 + 2) * 64 + r] = v4.z;
        sQt[(d0 + 3) * 64 + r] = v4.w;
    }
    if (tid < 64) { sM[tid] = -1e30f; sL[tid] = 0.0f; }

    // PV-stage thread mapping: 8 rows x 4 cols per thread
    const int r0 = (tid / 32) * 8;
    const int c0 = (tid % 32) * 4;
    float acc[8][4];
#pragma unroll
    for (int i = 0; i < 8; i++)
#pragma unroll
        for (int j = 0; j < 4; j++) acc[i][j] = 0.0f;

    // QK-stage thread mapping: 4 rows x 4 cols per thread
    const int rq = (tid / 16) * 4;
    const int cq = (tid % 16) * 4;

    // Softmax-stage mapping: 4 threads per row, 16 cols each (quad in-warp)
    const int srow = tid >> 2;        // 0..63
    const int sl4  = tid & 3;         // 0..3
    const int sc0  = sl4 * 16;

    for (int kt = 0; kt <= qt; kt++) {
        const int k0 = kt * BN;
        __syncthreads();  // previous PV stage done before overwriting K/V/P

        // Load K transposed, V row-major
#pragma unroll
        for (int s = 0; s < 8; s++) {
            int f  = tid + s * NTHREADS;
            int r  = f / 32;
            int d0 = (f % 32) * 4;
            float4 kv4 = *reinterpret_cast<const float4*>(&K[(size_t)(k0 + r) * HD + d0]);
            sKt[(d0 + 0) * 64 + r] = kv4.x;
            sKt[(d0 + 1) * 64 + r] = kv4.y;
            sKt[(d0 + 2) * 64 + r] = kv4.z;
            sKt[(d0 + 3) * 64 + r] = kv4.w;
            float4 vv4 = *reinterpret_cast<const float4*>(&V[(size_t)(k0 + r) * HD + d0]);
            *reinterpret_cast<float4*>(&sV[r * 128 + d0]) = vv4;
        }
        __syncthreads();

        // S = Q K^T * scale  (+ causal mask on the diagonal tile)
        {
            float s4[4][4];
#pragma unroll
            for (int i = 0; i < 4; i++)
#pragma unroll
                for (int j = 0; j < 4; j++) s4[i][j] = 0.0f;

#pragma unroll 4
            for (int d = 0; d < 128; d++) {
                float4 qa = *reinterpret_cast<float4*>(&sQt[d * 64 + rq]);
                float4 kb = *reinterpret_cast<float4*>(&sKt[d * 64 + cq]);
                float qr[4] = {qa.x, qa.y, qa.z, qa.w};
                float kr[4] = {kb.x, kb.y, kb.z, kb.w};
#pragma unroll
                for (int i = 0; i < 4; i++)
#pragma unroll
                    for (int j = 0; j < 4; j++)
                        s4[i][j] = fmaf(qr[i], kr[j], s4[i][j]);
            }
            const bool diag = (kt == qt);
#pragma unroll
            for (int i = 0; i < 4; i++) {
#pragma unroll
                for (int j = 0; j < 4; j++) {
                    float v = s4[i][j] * scale;
                    if (diag && (cq + j) > (rq + i)) v = -1e30f;
                    sP[(rq + i) * 65 + (cq + j)] = v;
                }
            }
        }
        __syncthreads();

        // Online softmax: 4 threads per row (consecutive lanes of one warp),
        // each covers 16 columns; quad reductions via shfl_xor.
        {
            float* prow = &sP[srow * 65 + sc0];
            float mt = -1e30f;
#pragma unroll
            for (int j = 0; j < 16; j++) mt = fmaxf(mt, prow[j]);
            mt = fmaxf(mt, __shfl_xor_sync(0xFFFFFFFFu, mt, 1));
            mt = fmaxf(mt, __shfl_xor_sync(0xFFFFFFFFu, mt, 2));

            float m0   = sM[srow];
            float mnew = fmaxf(m0, mt);

            float sum = 0.0f;
#pragma unroll
            for (int j = 0; j < 16; j++) {
                float p = __expf(prow[j] - mnew);
                prow[j] = p;
                sum += p;
            }
            sum += __shfl_xor_sync(0xFFFFFFFFu, sum, 1);
            sum += __shfl_xor_sync(0xFFFFFFFFu, sum, 2);

            if (sl4 == 0) {
                float corr = __expf(m0 - mnew);
                sL[srow] = sL[srow] * corr + sum;
                sM[srow] = mnew;
                sC[srow] = corr;
            }
        }
        __syncthreads();

        // Rescale accumulators and accumulate P @ V
#pragma unroll
        for (int i = 0; i < 8; i++) {
            float cr = sC[r0 + i];
#pragma unroll
            for (int j = 0; j < 4; j++) acc[i][j] *= cr;
        }
#pragma unroll 4
        for (int j = 0; j < BN; j++) {
            float4 v4 = *reinterpret_cast<float4*>(&sV[j * 128 + c0]);
#pragma unroll
            for (int i = 0; i < 8; i++) {
                float p = sP[(r0 + i) * 65 + j];
                acc[i][0] = fmaf(p, v4.x, acc[i][0]);
                acc[i][1] = fmaf(p, v4.y, acc[i][1]);
                acc[i][2] = fmaf(p, v4.z, acc[i][2]);
                acc[i][3] = fmaf(p, v4.w, acc[i][3]);
            }
        }
    }

    // Final normalize + store
    float* O = out + (size_t)b * SEQ * HD;
#pragma unroll
    for (int i = 0; i < 8; i++) {
        float inv = 1.0f / sL[r0 + i];
        float4 o;
        o.x = acc[i][0] * inv;
        o.y = acc[i][1] * inv;
        o.z = acc[i][2] * inv;
        o.w = acc[i][3] * inv;
        *reinterpret_cast<float4*>(&O[(size_t)(q0 + r0 + i) * HD + c0]) = o;
    }
}

// ---------------------------------------------------------------------------
extern "C" void kernel_launch(void* const* d_in, const int* in_sizes, int n_in,
                              void* d_out, int out_size)
{
    const float* x  = (const float*)d_in[0];
    const float* wq = (const float*)d_in[1];
    const float* bq = (const float*)d_in[2];
    const float* wk = (const float*)d_in[3];
    const float* bk = (const float*)d_in[4];
    const float* wv = (const float*)d_in[5];
    const float* bv = (const float*)d_in[6];
    float* out = (float*)d_out;

    // Projection: 128 row tiles x 3 weight matrices
    qkv_proj_kernel<<<dim3(128, 3), NTHREADS>>>(x, wq, bq, wk, bk, wv, bv);

    // Attention: 32 query tiles x 4 batches, 113 KB dynamic smem
    const int smem_bytes = (128 * 64 * 2 + 64 * 128 + 64 * 65 + 3 * 64) * sizeof(float);
    cudaFuncSetAttribute(attn_kernel, cudaFuncAttributeMaxDynamicSharedMemorySize,
                         smem_bytes);
    attn_kernel<<<dim3(SEQ / BM, BATCH), NTHREADS, smem_bytes>>>(out);
}

// round 3
// speedup vs baseline: 2.0512x; 2.0512x over previous
#include <cuda_runtime.h>
#include <math.h>
#include <stdint.h>

#define ED 1024
#define HD 128
#define BATCH 4
#define SEQ 2048
#define BM 64
#define BN 64
#define NTHREADS 256

// Padded shared-memory strides (floats)
#define QS 132   // sQ / sK row stride -> fragment LDS bank = lane (conflict-free)
#define VS 136   // sV row stride      -> PV A-frag LDS bank = 8*(lane&3)+(lane>>2) (conflict-free)
#define PS 68    // sP row stride      -> PV B-frag LDS bank = lane (conflict-free)

// Scratch for projected Q, K, V  (4 MB each)
__device__ float g_q[BATCH * SEQ * HD];
__device__ float g_k[BATCH * SEQ * HD];
__device__ float g_v[BATCH * SEQ * HD];

// ---------------------------------------------------------------------------
// Helpers
// ---------------------------------------------------------------------------
__device__ __forceinline__ uint32_t tf32_bits(float x) {
    uint32_t u;
    asm("cvt.rna.tf32.f32 %0, %1;" : "=r"(u) : "f"(x));
    return u;
}

__device__ __forceinline__ void mma_tf32(float c[4],
                                         uint32_t a0, uint32_t a1, uint32_t a2, uint32_t a3,
                                         uint32_t b0, uint32_t b1) {
    asm volatile(
        "mma.sync.aligned.m16n8k8.row.col.f32.tf32.tf32.f32 "
        "{%0,%1,%2,%3},{%4,%5,%6,%7},{%8,%9},{%0,%1,%2,%3};"
        : "+f"(c[0]), "+f"(c[1]), "+f"(c[2]), "+f"(c[3])
        : "r"(a0), "r"(a1), "r"(a2), "r"(a3), "r"(b0), "r"(b1));
}

// ---------------------------------------------------------------------------
// Kernel 1: fused QKV projection (unchanged fp32 baseline).
// ---------------------------------------------------------------------------
__global__ __launch_bounds__(NTHREADS) void qkv_proj_kernel(
    const float* __restrict__ x,
    const float* __restrict__ wq, const float* __restrict__ bq,
    const float* __restrict__ wk, const float* __restrict__ bk,
    const float* __restrict__ wv, const float* __restrict__ bv)
{
    const float* w;
    const float* bias;
    float* out;
    switch (blockIdx.y) {
        case 0:  w = wq; bias = bq; out = g_q; break;
        case 1:  w = wk; bias = bk; out = g_k; break;
        default: w = wv; bias = bv; out = g_v; break;
    }

    __shared__ float sX[32 * 64];
    __shared__ float sW[32 * 128];

    const int tid  = threadIdx.x;
    const int row0 = blockIdx.x * 64;
    const int r0   = (tid / 32) * 8;
    const int c0   = (tid % 32) * 4;

    float acc[8][4];
#pragma unroll
    for (int i = 0; i < 8; i++)
#pragma unroll
        for (int j = 0; j < 4; j++) acc[i][j] = 0.0f;

    for (int kt = 0; kt < ED; kt += 32) {
        __syncthreads();
#pragma unroll
        for (int s = 0; s < 2; s++) {
            int f   = tid + s * NTHREADS;
            int r   = f / 8;
            int kk0 = (f % 8) * 4;
            float4 v4 = *reinterpret_cast<const float4*>(
                &x[(size_t)(row0 + r) * ED + kt + kk0]);
            sX[(kk0 + 0) * 64 + r] = v4.x;
            sX[(kk0 + 1) * 64 + r] = v4.y;
            sX[(kk0 + 2) * 64 + r] = v4.z;
            sX[(kk0 + 3) * 64 + r] = v4.w;
        }
#pragma unroll
        for (int s = 0; s < 4; s++) {
            int f   = tid + s * NTHREADS;
            int kk  = f / 32;
            int cc  = (f % 32) * 4;
            *reinterpret_cast<float4*>(&sW[kk * 128 + cc]) =
                *reinterpret_cast<const float4*>(&w[(size_t)(kt + kk) * HD + cc]);
        }
        __syncthreads();

#pragma unroll
        for (int kk = 0; kk < 32; kk++) {
            float4 xa = *reinterpret_cast<float4*>(&sX[kk * 64 + r0]);
            float4 xb = *reinterpret_cast<float4*>(&sX[kk * 64 + r0 + 4]);
            float4 wv4 = *reinterpret_cast<float4*>(&sW[kk * 128 + c0]);
            float xr[8] = {xa.x, xa.y, xa.z, xa.w, xb.x, xb.y, xb.z, xb.w};
            float wr[4] = {wv4.x, wv4.y, wv4.z, wv4.w};
#pragma unroll
            for (int i = 0; i < 8; i++)
#pragma unroll
                for (int j = 0; j < 4; j++)
                    acc[i][j] = fmaf(xr[i], wr[j], acc[i][j]);
        }
    }

#pragma unroll
    for (int i = 0; i < 8; i++) {
        float4 o;
        o.x = acc[i][0] + bias[c0 + 0];
        o.y = acc[i][1] + bias[c0 + 1];
        o.z = acc[i][2] + bias[c0 + 2];
        o.w = acc[i][3] + bias[c0 + 3];
        *reinterpret_cast<float4*>(&out[(size_t)(row0 + r0 + i) * HD + c0]) = o;
    }
}

// ---------------------------------------------------------------------------
// Kernel 2: causal flash attention with tf32 mma.sync tensor cores.
// BM=BN=64, D=128, 8 warps.
//  QK stage: warp grid 4(m) x 2(n); warp tile 16x32 of S.
//  PV stage: computes O^T = V^T * P^T; 8 warps along d (16 each), n = 64 q-rows.
// ---------------------------------------------------------------------------
__global__ __launch_bounds__(NTHREADS) void attn_kernel(float* __restrict__ out)
{
    extern __shared__ float smbuf[];
    float* sQ = smbuf;                 // [64][QS]
    float* sK = sQ + 64 * QS;          // [64][QS]
    float* sV = sK + 64 * QS;          // [64][VS]
    float* sP = sV + 64 * VS;          // [64][PS]
    float* sM = sP + 64 * PS;
    float* sL = sM + 64;
    float* sC = sL + 64;

    const int tid  = threadIdx.x;
    const int lane = tid & 31;
    const int wid  = tid >> 5;
    const int l4   = lane & 3;   // threadID_in_group (k / col pair index)
    const int g8   = lane >> 2;  // groupID (row index)

    const int b  = blockIdx.y;
    const int qt = blockIdx.x;
    const int q0 = qt * BM;

    const float* Q = g_q + (size_t)b * SEQ * HD;
    const float* K = g_k + (size_t)b * SEQ * HD;
    const float* V = g_v + (size_t)b * SEQ * HD;

    const float scale = 0.08838834764831845f;  // 1/sqrt(128)

    // ---- load Q tile (tf32-converted), row-major padded ----
#pragma unroll
    for (int s = 0; s < 8; s++) {
        int f  = tid + s * NTHREADS;   // 2048 float4
        int r  = f >> 5;
        int k0 = (f & 31) * 4;
        float4 v4 = *reinterpret_cast<const float4*>(&Q[(size_t)(q0 + r) * HD + k0]);
        float4 t4;
        t4.x = __uint_as_float(tf32_bits(v4.x));
        t4.y = __uint_as_float(tf32_bits(v4.y));
        t4.z = __uint_as_float(tf32_bits(v4.z));
        t4.w = __uint_as_float(tf32_bits(v4.w));
        *reinterpret_cast<float4*>(&sQ[r * QS + k0]) = t4;
    }
    if (tid < 64) { sM[tid] = -1e30f; sL[tid] = 0.0f; }

    // QK warp mapping
    const int wm = wid >> 1;
    const int wn = wid & 1;
    const int m0 = wm * 16;
    const int n0 = wn * 32;

    // PV warp mapping (d dimension)
    const int d0 = wid * 16;

    // Softmax mapping: 4 threads per row
    const int srow = tid >> 2;
    const int sl4  = tid & 3;
    const int sc0  = sl4 * 16;

    // Persistent O^T accumulators: 8 n-frags x 4
    float cO[8][4];
#pragma unroll
    for (int i = 0; i < 8; i++)
#pragma unroll
        for (int j = 0; j < 4; j++) cO[i][j] = 0.0f;

    for (int kt = 0; kt <= qt; kt++) {
        const int k0g = kt * BN;
        __syncthreads();   // previous PV done before overwriting K/V

        // ---- fill K (sK) and V (sV), tf32-converted ----
#pragma unroll
        for (int s = 0; s < 8; s++) {
            int f  = tid + s * NTHREADS;
            int r  = f >> 5;
            int c  = (f & 31) * 4;
            float4 kv = *reinterpret_cast<const float4*>(&K[(size_t)(k0g + r) * HD + c]);
            float4 tk;
            tk.x = __uint_as_float(tf32_bits(kv.x));
            tk.y = __uint_as_float(tf32_bits(kv.y));
            tk.z = __uint_as_float(tf32_bits(kv.z));
            tk.w = __uint_as_float(tf32_bits(kv.w));
            *reinterpret_cast<float4*>(&sK[r * QS + c]) = tk;

            float4 vv = *reinterpret_cast<const float4*>(&V[(size_t)(k0g + r) * HD + c]);
            float4 tv;
            tv.x = __uint_as_float(tf32_bits(vv.x));
            tv.y = __uint_as_float(tf32_bits(vv.y));
            tv.z = __uint_as_float(tf32_bits(vv.z));
            tv.w = __uint_as_float(tf32_bits(vv.w));
            *reinterpret_cast<float4*>(&sV[r * VS + c]) = tv;
        }
        __syncthreads();

        // ---- S = Q K^T (tf32 mma), warp tile 16x32 ----
        float cS[4][4];
#pragma unroll
        for (int i = 0; i < 4; i++)
#pragma unroll
            for (int j = 0; j < 4; j++) cS[i][j] = 0.0f;

#pragma unroll
        for (int kk = 0; kk < HD; kk += 8) {
            const float* aq = &sQ[(m0 + g8) * QS + kk + l4];
            uint32_t a0 = __float_as_uint(aq[0]);
            uint32_t a1 = __float_as_uint(aq[8 * QS]);
            uint32_t a2 = __float_as_uint(aq[4]);
            uint32_t a3 = __float_as_uint(aq[8 * QS + 4]);
#pragma unroll
            for (int nf = 0; nf < 4; nf++) {
                const float* bk = &sK[(n0 + nf * 8 + g8) * QS + kk + l4];
                uint32_t b0 = __float_as_uint(bk[0]);
                uint32_t b1 = __float_as_uint(bk[4]);
                mma_tf32(cS[nf], a0, a1, a2, a3, b0, b1);
            }
        }

        // ---- scale + causal mask + store S to sP ----
        {
            const bool diag = (kt == qt);
            const int row_a = m0 + g8;
            const int row_b = row_a + 8;
#pragma unroll
            for (int nf = 0; nf < 4; nf++) {
                int col = n0 + nf * 8 + 2 * l4;
                float v0 = cS[nf][0] * scale;
                float v1 = cS[nf][1] * scale;
                float v2 = cS[nf][2] * scale;
                float v3 = cS[nf][3] * scale;
                if (diag) {
                    if (col     > row_a) v0 = -1e30f;
                    if (col + 1 > row_a) v1 = -1e30f;
                    if (col     > row_b) v2 = -1e30f;
                    if (col + 1 > row_b) v3 = -1e30f;
                }
                *reinterpret_cast<float2*>(&sP[row_a * PS + col]) = make_float2(v0, v1);
                *reinterpret_cast<float2*>(&sP[row_b * PS + col]) = make_float2(v2, v3);
            }
        }
        __syncthreads();

        // ---- online softmax: 4 threads/row, quad shfl reductions ----
        {
            float* prow = &sP[srow * PS + sc0];
            float mt = -1e30f;
#pragma unroll
            for (int j = 0; j < 16; j++) mt = fmaxf(mt, prow[j]);
            mt = fmaxf(mt, __shfl_xor_sync(0xFFFFFFFFu, mt, 1));
            mt = fmaxf(mt, __shfl_xor_sync(0xFFFFFFFFu, mt, 2));

            float m0v  = sM[srow];
            float mnew = fmaxf(m0v, mt);

            float sum = 0.0f;
#pragma unroll
            for (int j = 0; j < 16; j++) {
                float p = __expf(prow[j] - mnew);
                float pr = __uint_as_float(tf32_bits(p));  // round once, use everywhere
                prow[j] = pr;
                sum += pr;
            }
            sum += __shfl_xor_sync(0xFFFFFFFFu, sum, 1);
            sum += __shfl_xor_sync(0xFFFFFFFFu, sum, 2);

            if (sl4 == 0) {
                float corr = __expf(m0v - mnew);
                sL[srow] = sL[srow] * corr + sum;
                sM[srow] = mnew;
                sC[srow] = corr;
            }
        }
        __syncthreads();

        // ---- rescale O^T accumulators by per-q-row corr ----
#pragma unroll
        for (int nf = 0; nf < 8; nf++) {
            int col = nf * 8 + 2 * l4;
            float cr0 = sC[col];
            float cr1 = sC[col + 1];
            cO[nf][0] *= cr0;
            cO[nf][1] *= cr1;
            cO[nf][2] *= cr0;
            cO[nf][3] *= cr1;
        }

        // ---- O^T += V^T @ P^T  (A = V^T from sV, B = P^T from sP) ----
#pragma unroll
        for (int kk = 0; kk < BN; kk += 8) {
            const float* av = &sV[(kk + l4) * VS + d0 + g8];
            uint32_t a0 = __float_as_uint(av[0]);
            uint32_t a1 = __float_as_uint(av[8]);
            uint32_t a2 = __float_as_uint(av[4 * VS]);
            uint32_t a3 = __float_as_uint(av[4 * VS + 8]);
#pragma unroll
            for (int nf = 0; nf < 8; nf++) {
                const float* bp = &sP[(nf * 8 + g8) * PS + kk + l4];
                uint32_t b0 = __float_as_uint(bp[0]);
                uint32_t b1 = __float_as_uint(bp[4]);
                mma_tf32(cO[nf], a0, a1, a2, a3, b0, b1);
            }
        }
    }

    // ---- epilogue: normalize by 1/L and store (O^T frags -> [q][d]) ----
    __syncthreads();
    float* O = out + (size_t)b * SEQ * HD;
#pragma unroll
    for (int nf = 0; nf < 8; nf++) {
        int col0 = nf * 8 + 2 * l4;
        int col1 = col0 + 1;
        float inv0 = 1.0f / sL[col0];
        float inv1 = 1.0f / sL[col1];
        int d = d0 + g8;
        O[(size_t)(q0 + col0) * HD + d]     = cO[nf][0] * inv0;
        O[(size_t)(q0 + col1) * HD + d]     = cO[nf][1] * inv1;
        O[(size_t)(q0 + col0) * HD + d + 8] = cO[nf][2] * inv0;
        O[(size_t)(q0 + col1) * HD + d + 8] = cO[nf][3] * inv1;
    }
}

// ---------------------------------------------------------------------------
extern "C" void kernel_launch(void* const* d_in, const int* in_sizes, int n_in,
                              void* d_out, int out_size)
{
    const float* x  = (const float*)d_in[0];
    const float* wq = (const float*)d_in[1];
    const float* bq = (const float*)d_in[2];
    const float* wk = (const float*)d_in[3];
    const float* bk = (const float*)d_in[4];
    const float* wv = (const float*)d_in[5];
    const float* bv = (const float*)d_in[6];
    float* out = (float*)d_out;

    qkv_proj_kernel<<<dim3(128, 3), NTHREADS>>>(x, wq, bq, wk, bk, wv, bv);

    const int smem_bytes =
        (64 * QS * 2 + 64 * VS + 64 * PS + 3 * 64) * sizeof(float);  // ~118 KB
    cudaFuncSetAttribute(attn_kernel, cudaFuncAttributeMaxDynamicSharedMemorySize,
                         smem_bytes);
    attn_kernel<<<dim3(SEQ / BM, BATCH), NTHREADS, smem_bytes>>>(out);
}

// round 8
// speedup vs baseline: 2.5715x; 1.2537x over previous
#include <cuda_runtime.h>
#include <math.h>
#include <stdint.h>

#define ED 1024
#define HD 128
#define BATCH 4
#define SEQ 2048
#define BM 64
#define BN 64
#define NTHREADS 256
#define ATHREADS 512

// attn smem strides (floats)
#define QS 132
#define VS 136
#define PS 68

// proj smem strides
#define XS 36
#define WS 36

// split-K chunking: chunks of up to 8 k-tiles (512 keys)
#define CHTILES 8
#define CH_PER_BATCH 80          // sum over qt of (qt/8+1)
#define CHUNKS_TOTAL (CH_PER_BATCH * BATCH)   // 320

// Scratch
__device__ float g_q[BATCH * SEQ * HD];
__device__ float g_k[BATCH * SEQ * HD];
__device__ float g_v[BATCH * SEQ * HD];
__device__ float g_po[CHUNKS_TOTAL * BM * HD];   // partial O' (unnormalized)
__device__ float g_pm[CHUNKS_TOTAL * BM];        // partial row max
__device__ float g_pl[CHUNKS_TOTAL * BM];        // partial row sumexp

// ---------------------------------------------------------------------------
__device__ __forceinline__ uint32_t tf32_bits(float x) {
    uint32_t u;
    asm("cvt.rna.tf32.f32 %0, %1;" : "=r"(u) : "f"(x));
    return u;
}

__device__ __forceinline__ void mma_tf32(float c[4],
                                         uint32_t a0, uint32_t a1, uint32_t a2, uint32_t a3,
                                         uint32_t b0, uint32_t b1) {
    asm volatile(
        "mma.sync.aligned.m16n8k8.row.col.f32.tf32.tf32.f32 "
        "{%0,%1,%2,%3},{%4,%5,%6,%7},{%8,%9},{%0,%1,%2,%3};"
        : "+f"(c[0]), "+f"(c[1]), "+f"(c[2]), "+f"(c[3])
        : "r"(a0), "r"(a1), "r"(a2), "r"(a3), "r"(b0), "r"(b1));
}

// ---------------------------------------------------------------------------
// Kernel 1: fused QKV projection via tf32 mma.sync (256 threads).
// C[64][128] = X[64][1024] @ W[1024][128] + b
// 8 warps: 2(m) x 4(n); warp tile 32x32.
// ---------------------------------------------------------------------------
__global__ __launch_bounds__(NTHREADS) void qkv_proj_kernel(
    const float* __restrict__ x,
    const float* __restrict__ wq, const float* __restrict__ bq,
    const float* __restrict__ wk, const float* __restrict__ bk,
    const float* __restrict__ wv, const float* __restrict__ bv)
{
    const float* w;
    const float* bias;
    float* out;
    switch (blockIdx.y) {
        case 0:  w = wq; bias = bq; out = g_q; break;
        case 1:  w = wk; bias = bk; out = g_k; break;
        default: w = wv; bias = bv; out = g_v; break;
    }

    __shared__ float sX[64 * XS];     // [row][k], tf32
    __shared__ float sWt[128 * WS];   // [n][k],   tf32 (W transposed)

    const int tid  = threadIdx.x;
    const int lane = tid & 31;
    const int wid  = tid >> 5;
    const int l4   = lane & 3;
    const int g8   = lane >> 2;

    const int row0 = blockIdx.x * 64;
    const int m0   = (wid >> 2) * 32;   // 0 or 32
    const int n0   = (wid & 3) * 32;    // 0,32,64,96

    float acc[2][4][4];
#pragma unroll
    for (int mf = 0; mf < 2; mf++)
#pragma unroll
        for (int nf = 0; nf < 4; nf++)
#pragma unroll
            for (int j = 0; j < 4; j++) acc[mf][nf][j] = 0.0f;

    for (int kt = 0; kt < ED; kt += 32) {
        __syncthreads();
        // X tile 64x32 -> sX row-major, tf32
#pragma unroll
        for (int s = 0; s < 2; s++) {
            int f   = tid + s * NTHREADS;      // 512 float4
            int r   = f >> 3;
            int kk0 = (f & 7) * 4;
            float4 v4 = *reinterpret_cast<const float4*>(
                &x[(size_t)(row0 + r) * ED + kt + kk0]);
            float4 t4;
            t4.x = __uint_as_float(tf32_bits(v4.x));
            t4.y = __uint_as_float(tf32_bits(v4.y));
            t4.z = __uint_as_float(tf32_bits(v4.z));
            t4.w = __uint_as_float(tf32_bits(v4.w));
            *reinterpret_cast<float4*>(&sX[r * XS + kk0]) = t4;
        }
        // W tile 32x128 -> sWt transposed [n][k], tf32
#pragma unroll
        for (int s = 0; s < 4; s++) {
            int f  = tid + s * NTHREADS;       // 1024 float4
            int kk = f >> 5;
            int c0 = (f & 31) * 4;
            float4 v4 = *reinterpret_cast<const float4*>(
                &w[(size_t)(kt + kk) * HD + c0]);
            sWt[(c0 + 0) * WS + kk] = __uint_as_float(tf32_bits(v4.x));
            sWt[(c0 + 1) * WS + kk] = __uint_as_float(tf32_bits(v4.y));
            sWt[(c0 + 2) * WS + kk] = __uint_as_float(tf32_bits(v4.z));
            sWt[(c0 + 3) * WS + kk] = __uint_as_float(tf32_bits(v4.w));
        }
        __syncthreads();

#pragma unroll
        for (int kk = 0; kk < 32; kk += 8) {
#pragma unroll
            for (int mf = 0; mf < 2; mf++) {
                const float* ax = &sX[(m0 + mf * 16 + g8) * XS + kk + l4];
                uint32_t a0 = __float_as_uint(ax[0]);
                uint32_t a1 = __float_as_uint(ax[8 * XS]);
                uint32_t a2 = __float_as_uint(ax[4]);
                uint32_t a3 = __float_as_uint(ax[8 * XS + 4]);
#pragma unroll
                for (int nf = 0; nf < 4; nf++) {
                    const float* bw = &sWt[(n0 + nf * 8 + g8) * WS + kk + l4];
                    uint32_t b0 = __float_as_uint(bw[0]);
                    uint32_t b1 = __float_as_uint(bw[4]);
                    mma_tf32(acc[mf][nf], a0, a1, a2, a3, b0, b1);
                }
            }
        }
    }

    // epilogue: + bias, store
#pragma unroll
    for (int mf = 0; mf < 2; mf++) {
        int ra = m0 + mf * 16 + g8;
        int rb = ra + 8;
#pragma unroll
        for (int nf = 0; nf < 4; nf++) {
            int col = n0 + nf * 8 + 2 * l4;
            float b0v = bias[col];
            float b1v = bias[col + 1];
            *reinterpret_cast<float2*>(&out[(size_t)(row0 + ra) * HD + col]) =
                make_float2(acc[mf][nf][0] + b0v, acc[mf][nf][1] + b1v);
            *reinterpret_cast<float2*>(&out[(size_t)(row0 + rb) * HD + col]) =
                make_float2(acc[mf][nf][2] + b0v, acc[mf][nf][3] + b1v);
        }
    }
}

// ---------------------------------------------------------------------------
// Kernel 2: split-K causal flash attention chunk (tf32 mma), 512 threads.
// One CTA = one (batch, q-tile, k-chunk of <=8 tiles). Emits unnormalized
// partial O', row max m, row sumexp l.
//  QK: 16 warps = 4(m) x 4(n), warp tile 16x16 of S.
//  PV: 16 warps = 8 d-tiles x 2 q-halves; warp computes 16(d) x 32(q) of O^T.
// ---------------------------------------------------------------------------
__global__ __launch_bounds__(ATHREADS) void attn_chunk_kernel()
{
    extern __shared__ float smbuf[];
    float* sQ = smbuf;                 // [64][QS]
    float* sK = sQ + 64 * QS;
    float* sV = sK + 64 * QS;          // [64][VS]
    float* sP = sV + 64 * VS;          // [64][PS]
    float* sM = sP + 64 * PS;
    float* sL = sM + 64;
    float* sC = sL + 64;

    const int tid  = threadIdx.x;
    const int lane = tid & 31;
    const int wid  = tid >> 5;         // 0..15
    const int l4   = lane & 3;
    const int g8   = lane >> 2;

    // decode chunk id -> (b, qt, ck)
    const int cid = blockIdx.x;
    const int b   = cid / CH_PER_BATCH;
    const int f   = cid % CH_PER_BATCH;
    int qt, ck;
    if (f < 8)        { qt = f;                 ck = 0; }
    else if (f < 24)  { qt = 8  + (f - 8)  / 2; ck = (f - 8)  % 2; }
    else if (f < 48)  { qt = 16 + (f - 24) / 3; ck = (f - 24) % 3; }
    else              { qt = 24 + (f - 48) / 4; ck = (f - 48) % 4; }

    const int kt_begin = ck * CHTILES;
    int kt_end = kt_begin + CHTILES;
    if (kt_end > qt + 1) kt_end = qt + 1;

    const int q0 = qt * BM;
    const float* Q = g_q + (size_t)b * SEQ * HD;
    const float* K = g_k + (size_t)b * SEQ * HD;
    const float* V = g_v + (size_t)b * SEQ * HD;

    const float scale = 0.08838834764831845f;

    // load Q tile (tf32): 2048 float4 over 512 threads
#pragma unroll
    for (int s = 0; s < 4; s++) {
        int ff = tid + s * ATHREADS;
        int r  = ff >> 5;
        int k0 = (ff & 31) * 4;
        float4 v4 = *reinterpret_cast<const float4*>(&Q[(size_t)(q0 + r) * HD + k0]);
        float4 t4;
        t4.x = __uint_as_float(tf32_bits(v4.x));
        t4.y = __uint_as_float(tf32_bits(v4.y));
        t4.z = __uint_as_float(tf32_bits(v4.z));
        t4.w = __uint_as_float(tf32_bits(v4.w));
        *reinterpret_cast<float4*>(&sQ[r * QS + k0]) = t4;
    }
    if (tid < 64) { sM[tid] = -1e30f; sL[tid] = 0.0f; }

    // QK warp mapping: 4(m) x 4(n), warp tile 16x16
    const int m0 = (wid >> 2) * 16;
    const int n0 = (wid & 3) * 16;

    // PV warp mapping: 8 d-tiles x 2 q-halves
    const int d0    = (wid >> 1) * 16;   // d tile base
    const int nbase = (wid & 1) * 4;     // n-frag base (q-rows nbase*8 .. +32)

    // Softmax mapping: 8 threads per row, 8 cols each (within-warp octet)
    const int srow = tid >> 3;           // 0..63
    const int sl8  = tid & 7;
    const int sc0  = sl8 * 8;

    float cO[4][4];
#pragma unroll
    for (int i = 0; i < 4; i++)
#pragma unroll
        for (int j = 0; j < 4; j++) cO[i][j] = 0.0f;

    for (int kt = kt_begin; kt < kt_end; kt++) {
        const int k0g = kt * BN;
        __syncthreads();

        // fill K and V tiles (tf32): 2048 float4 each over 512 threads
#pragma unroll
        for (int s = 0; s < 4; s++) {
            int ff = tid + s * ATHREADS;
            int r  = ff >> 5;
            int c  = (ff & 31) * 4;
            float4 kv = *reinterpret_cast<const float4*>(&K[(size_t)(k0g + r) * HD + c]);
            float4 tk;
            tk.x = __uint_as_float(tf32_bits(kv.x));
            tk.y = __uint_as_float(tf32_bits(kv.y));
            tk.z = __uint_as_float(tf32_bits(kv.z));
            tk.w = __uint_as_float(tf32_bits(kv.w));
            *reinterpret_cast<float4*>(&sK[r * QS + c]) = tk;

            float4 vv = *reinterpret_cast<const float4*>(&V[(size_t)(k0g + r) * HD + c]);
            float4 tv;
            tv.x = __uint_as_float(tf32_bits(vv.x));
            tv.y = __uint_as_float(tf32_bits(vv.y));
            tv.z = __uint_as_float(tf32_bits(vv.z));
            tv.w = __uint_as_float(tf32_bits(vv.w));
            *reinterpret_cast<float4*>(&sV[r * VS + c]) = tv;
        }
        __syncthreads();

        // S = Q K^T (warp tile 16x16 -> 2 n-frags)
        float cS[2][4];
#pragma unroll
        for (int i = 0; i < 2; i++)
#pragma unroll
            for (int j = 0; j < 4; j++) cS[i][j] = 0.0f;

#pragma unroll
        for (int kk = 0; kk < HD; kk += 8) {
            const float* aq = &sQ[(m0 + g8) * QS + kk + l4];
            uint32_t a0 = __float_as_uint(aq[0]);
            uint32_t a1 = __float_as_uint(aq[8 * QS]);
            uint32_t a2 = __float_as_uint(aq[4]);
            uint32_t a3 = __float_as_uint(aq[8 * QS + 4]);
#pragma unroll
            for (int nf = 0; nf < 2; nf++) {
                const float* bk = &sK[(n0 + nf * 8 + g8) * QS + kk + l4];
                uint32_t b0 = __float_as_uint(bk[0]);
                uint32_t b1 = __float_as_uint(bk[4]);
                mma_tf32(cS[nf], a0, a1, a2, a3, b0, b1);
            }
        }

        // scale + causal mask -> sP
        {
            const bool diag = (kt == qt);
            const int row_a = m0 + g8;
            const int row_b = row_a + 8;
#pragma unroll
            for (int nf = 0; nf < 2; nf++) {
                int col = n0 + nf * 8 + 2 * l4;
                float v0 = cS[nf][0] * scale;
                float v1 = cS[nf][1] * scale;
                float v2 = cS[nf][2] * scale;
                float v3 = cS[nf][3] * scale;
                if (diag) {
                    if (col     > row_a) v0 = -1e30f;
                    if (col + 1 > row_a) v1 = -1e30f;
                    if (col     > row_b) v2 = -1e30f;
                    if (col + 1 > row_b) v3 = -1e30f;
                }
                *reinterpret_cast<float2*>(&sP[row_a * PS + col]) = make_float2(v0, v1);
                *reinterpret_cast<float2*>(&sP[row_b * PS + col]) = make_float2(v2, v3);
            }
        }
        __syncthreads();

        // online softmax: 8 threads/row, octet shfl reductions
        {
            float* prow = &sP[srow * PS + sc0];
            float mt = -1e30f;
#pragma unroll
            for (int j = 0; j < 8; j++) mt = fmaxf(mt, prow[j]);
            mt = fmaxf(mt, __shfl_xor_sync(0xFFFFFFFFu, mt, 1));
            mt = fmaxf(mt, __shfl_xor_sync(0xFFFFFFFFu, mt, 2));
            mt = fmaxf(mt, __shfl_xor_sync(0xFFFFFFFFu, mt, 4));

            float m0v  = sM[srow];
            float mnew = fmaxf(m0v, mt);

            float sum = 0.0f;
#pragma unroll
            for (int j = 0; j < 8; j++) {
                float p = __expf(prow[j] - mnew);
                float pr = __uint_as_float(tf32_bits(p));
                prow[j] = pr;
                sum += pr;
            }
            sum += __shfl_xor_sync(0xFFFFFFFFu, sum, 1);
            sum += __shfl_xor_sync(0xFFFFFFFFu, sum, 2);
            sum += __shfl_xor_sync(0xFFFFFFFFu, sum, 4);

            if (sl8 == 0) {
                float corr = __expf(m0v - mnew);
                sL[srow] = sL[srow] * corr + sum;
                sM[srow] = mnew;
                sC[srow] = corr;
            }
        }
        __syncthreads();

        // rescale O^T accumulators by per-q-row corr
#pragma unroll
        for (int nf = 0; nf < 4; nf++) {
            int col = (nbase + nf) * 8 + 2 * l4;
            float cr0 = sC[col];
            float cr1 = sC[col + 1];
            cO[nf][0] *= cr0;
            cO[nf][1] *= cr1;
            cO[nf][2] *= cr0;
            cO[nf][3] *= cr1;
        }

        // O^T += V^T @ P^T  (A = V^T from sV, B = P^T from sP)
#pragma unroll
        for (int kk = 0; kk < BN; kk += 8) {
            const float* av = &sV[(kk + l4) * VS + d0 + g8];
            uint32_t a0 = __float_as_uint(av[0]);
            uint32_t a1 = __float_as_uint(av[8]);
            uint32_t a2 = __float_as_uint(av[4 * VS]);
            uint32_t a3 = __float_as_uint(av[4 * VS + 8]);
#pragma unroll
            for (int nf = 0; nf < 4; nf++) {
                const float* bp = &sP[((nbase + nf) * 8 + g8) * PS + kk + l4];
                uint32_t b0 = __float_as_uint(bp[0]);
                uint32_t b1 = __float_as_uint(bp[4]);
                mma_tf32(cO[nf], a0, a1, a2, a3, b0, b1);
            }
        }
    }

    // epilogue: write unnormalized partials + (m, l)
    __syncthreads();
    float* PO = g_po + (size_t)cid * BM * HD;
#pragma unroll
    for (int nf = 0; nf < 4; nf++) {
        int col0 = (nbase + nf) * 8 + 2 * l4;
        int d = d0 + g8;
        PO[(col0    ) * HD + d]     = cO[nf][0];
        PO[(col0 + 1) * HD + d]     = cO[nf][1];
        PO[(col0    ) * HD + d + 8] = cO[nf][2];
        PO[(col0 + 1) * HD + d + 8] = cO[nf][3];
    }
    if (tid < 64) {
        g_pm[cid * BM + tid] = sM[tid];
        g_pl[cid * BM + tid] = sL[tid];
    }
}

// ---------------------------------------------------------------------------
// Kernel 3: combine partial chunks.  grid (32 qt, 4 b), 256 threads.
// ---------------------------------------------------------------------------
__global__ __launch_bounds__(NTHREADS) void attn_combine_kernel(float* __restrict__ out)
{
    __shared__ float sW[4][64];
    __shared__ float sLinv[64];

    const int tid = threadIdx.x;
    const int qt  = blockIdx.x;
    const int b   = blockIdx.y;
    const int q0  = qt * BM;

    // chunk range for this (b, qt)
    int start;
    if (qt < 8)       start = qt;
    else if (qt < 16) start = 8  + 2 * (qt - 8);
    else if (qt < 24) start = 24 + 3 * (qt - 16);
    else              start = 48 + 4 * (qt - 24);
    const int nc   = qt / 8 + 1;
    const int base = b * CH_PER_BATCH + start;

    // per-row weights
    if (tid < 64) {
        const int r = tid;
        float M = -1e30f;
        float mv[4];
        for (int c = 0; c < nc; c++) {
            mv[c] = g_pm[(base + c) * BM + r];
            M = fmaxf(M, mv[c]);
        }
        float L = 0.0f;
        for (int c = 0; c < nc; c++) {
            float wc = __expf(mv[c] - M);
            sW[c][r] = wc;
            L += wc * g_pl[(base + c) * BM + r];
        }
        sLinv[r] = 1.0f / L;
    }
    __syncthreads();

    float* O = out + ((size_t)b * SEQ + q0) * HD;
#pragma unroll 4
    for (int s = 0; s < 32; s++) {
        int e = tid + s * NTHREADS;   // 0..8191
        int r = e >> 7;
        float acc = 0.0f;
        for (int c = 0; c < nc; c++)
            acc += sW[c][r] * g_po[(size_t)(base + c) * BM * HD + e];
        O[e] = acc * sLinv[r];
    }
}

// ---------------------------------------------------------------------------
extern "C" void kernel_launch(void* const* d_in, const int* in_sizes, int n_in,
                              void* d_out, int out_size)
{
    const float* x  = (const float*)d_in[0];
    const float* wq = (const float*)d_in[1];
    const float* bq = (const float*)d_in[2];
    const float* wk = (const float*)d_in[3];
    const float* bk = (const float*)d_in[4];
    const float* wv = (const float*)d_in[5];
    const float* bv = (const float*)d_in[6];
    float* out = (float*)d_out;

    qkv_proj_kernel<<<dim3(128, 3), NTHREADS>>>(x, wq, bq, wk, bk, wv, bv);

    const int smem_bytes =
        (64 * QS * 2 + 64 * VS + 64 * PS + 3 * 64) * sizeof(float);
    cudaFuncSetAttribute(attn_chunk_kernel, cudaFuncAttributeMaxDynamicSharedMemorySize,
                         smem_bytes);
    attn_chunk_kernel<<<CHUNKS_TOTAL, ATHREADS, smem_bytes>>>();

    attn_combine_kernel<<<dim3(32, BATCH), NTHREADS>>>(out);
}

// round 9
// speedup vs baseline: 4.2064x; 1.6357x over previous
#include <cuda_runtime.h>
#include <math.h>
#include <stdint.h>

#define ED 1024
#define HD 128
#define BATCH 4
#define SEQ 2048
#define BM 64
#define BN 64
#define NTHREADS 256
#define ATHREADS 512
#define PTHREADS 512

// attn smem strides (floats)
#define QS 132
#define VS 136
#define PS 68

// proj smem strides (floats)
#define XS 36     // sX row stride: A-frag bank = 4*g8+l4, conflict-free
#define WS2 136   // sW row stride: B-frag bank = 8*l4+g8, conflict-free; 136%32=8

// split-K chunking: chunks of up to 8 k-tiles (512 keys)
#define CHTILES 8
#define CH_PER_BATCH 80          // sum over qt of (qt/8+1)
#define CHUNKS_TOTAL (CH_PER_BATCH * BATCH)   // 320

// Scratch
__device__ float g_q[BATCH * SEQ * HD];
__device__ float g_k[BATCH * SEQ * HD];
__device__ float g_v[BATCH * SEQ * HD];
__device__ float g_po[CHUNKS_TOTAL * BM * HD];   // partial O' (unnormalized)
__device__ float g_pm[CHUNKS_TOTAL * BM];        // partial row max
__device__ float g_pl[CHUNKS_TOTAL * BM];        // partial row sumexp

// ---------------------------------------------------------------------------
__device__ __forceinline__ uint32_t tf32_bits(float x) {
    uint32_t u;
    asm("cvt.rna.tf32.f32 %0, %1;" : "=r"(u) : "f"(x));
    return u;
}

__device__ __forceinline__ void mma_tf32(float c[4],
                                         uint32_t a0, uint32_t a1, uint32_t a2, uint32_t a3,
                                         uint32_t b0, uint32_t b1) {
    asm volatile(
        "mma.sync.aligned.m16n8k8.row.col.f32.tf32.tf32.f32 "
        "{%0,%1,%2,%3},{%4,%5,%6,%7},{%8,%9},{%0,%1,%2,%3};"
        : "+f"(c[0]), "+f"(c[1]), "+f"(c[2]), "+f"(c[3])
        : "r"(a0), "r"(a1), "r"(a2), "r"(a3), "r"(b0), "r"(b1));
}

// ---------------------------------------------------------------------------
// Kernel 1: FUSED QKV projection, tf32 mma, 512 threads, one CTA per 64 rows.
//  - X tile loaded ONCE per kt, shared by all three outputs.
//  - W stored in natural [k][n] layout (no transpose; float4 STS; stride 136).
//  - A fragments reused register-side across the 3 B matrices.
//  16 warps: 2(m) x 8(n), warp tile 32x16 per output.
// ---------------------------------------------------------------------------
__global__ __launch_bounds__(PTHREADS) void qkv_proj_kernel(
    const float* __restrict__ x,
    const float* __restrict__ wq, const float* __restrict__ bq,
    const float* __restrict__ wk, const float* __restrict__ bk,
    const float* __restrict__ wv, const float* __restrict__ bv)
{
    extern __shared__ float psm[];
    float* sX  = psm;                       // [64][XS]
    float* sW0 = sX + 64 * XS;              // [32][WS2] per output
    float* sW1 = sW0 + 32 * WS2;
    float* sW2 = sW1 + 32 * WS2;

    const float* wptr[3]  = {wq, wk, wv};
    const float* bptr[3]  = {bq, bk, bv};
    float*       optr[3]  = {g_q, g_k, g_v};
    float*       swp[3]   = {sW0, sW1, sW2};

    const int tid  = threadIdx.x;
    const int lane = tid & 31;
    const int wid  = tid >> 5;      // 0..15
    const int l4   = lane & 3;
    const int g8   = lane >> 2;

    const int row0 = blockIdx.x * 64;
    const int m0   = (wid >> 3) * 32;   // 0 or 32
    const int n0   = (wid & 7) * 16;    // 0,16,...,112

    float acc[3][2][2][4];
#pragma unroll
    for (int o = 0; o < 3; o++)
#pragma unroll
        for (int mf = 0; mf < 2; mf++)
#pragma unroll
            for (int nf = 0; nf < 2; nf++)
#pragma unroll
                for (int j = 0; j < 4; j++) acc[o][mf][nf][j] = 0.0f;

    for (int kt = 0; kt < ED; kt += 32) {
        __syncthreads();
        // X tile 64x32 -> sX row-major, tf32 (512 float4, 1 per thread)
        {
            int r   = tid >> 3;
            int kk0 = (tid & 7) * 4;
            float4 v4 = *reinterpret_cast<const float4*>(
                &x[(size_t)(row0 + r) * ED + kt + kk0]);
            float4 t4;
            t4.x = __uint_as_float(tf32_bits(v4.x));
            t4.y = __uint_as_float(tf32_bits(v4.y));
            t4.z = __uint_as_float(tf32_bits(v4.z));
            t4.w = __uint_as_float(tf32_bits(v4.w));
            *reinterpret_cast<float4*>(&sX[r * XS + kk0]) = t4;
        }
        // W tiles 32x128 each, natural [k][n] layout, float4 STS
#pragma unroll
        for (int o = 0; o < 3; o++) {
            const float* w = wptr[o];
            float* sW = swp[o];
#pragma unroll
            for (int s = 0; s < 2; s++) {
                int f  = tid + s * PTHREADS;     // 1024 float4
                int kk = f >> 5;
                int c0 = (f & 31) * 4;
                float4 v4 = *reinterpret_cast<const float4*>(
                    &w[(size_t)(kt + kk) * HD + c0]);
                float4 t4;
                t4.x = __uint_as_float(tf32_bits(v4.x));
                t4.y = __uint_as_float(tf32_bits(v4.y));
                t4.z = __uint_as_float(tf32_bits(v4.z));
                t4.w = __uint_as_float(tf32_bits(v4.w));
                *reinterpret_cast<float4*>(&sW[kk * WS2 + c0]) = t4;
            }
        }
        __syncthreads();

#pragma unroll
        for (int kk = 0; kk < 32; kk += 8) {
            // A fragments (X), loaded once, reused for all 3 outputs
            uint32_t a[2][4];
#pragma unroll
            for (int mf = 0; mf < 2; mf++) {
                const float* ax = &sX[(m0 + mf * 16 + g8) * XS + kk + l4];
                a[mf][0] = __float_as_uint(ax[0]);
                a[mf][1] = __float_as_uint(ax[8 * XS]);
                a[mf][2] = __float_as_uint(ax[4]);
                a[mf][3] = __float_as_uint(ax[8 * XS + 4]);
            }
#pragma unroll
            for (int o = 0; o < 3; o++) {
                const float* sW = swp[o];
#pragma unroll
                for (int nf = 0; nf < 2; nf++) {
                    // B col-major fragment read directly from [k][n] layout
                    const float* bw = &sW[(kk + l4) * WS2 + n0 + nf * 8 + g8];
                    uint32_t b0 = __float_as_uint(bw[0]);
                    uint32_t b1 = __float_as_uint(bw[4 * WS2]);
#pragma unroll
                    for (int mf = 0; mf < 2; mf++)
                        mma_tf32(acc[o][mf][nf], a[mf][0], a[mf][1], a[mf][2], a[mf][3],
                                 b0, b1);
                }
            }
        }
    }

    // epilogue: + bias, store
#pragma unroll
    for (int o = 0; o < 3; o++) {
        const float* bias = bptr[o];
        float* out = optr[o];
#pragma unroll
        for (int mf = 0; mf < 2; mf++) {
            int ra = m0 + mf * 16 + g8;
            int rb = ra + 8;
#pragma unroll
            for (int nf = 0; nf < 2; nf++) {
                int col = n0 + nf * 8 + 2 * l4;
                float b0v = bias[col];
                float b1v = bias[col + 1];
                *reinterpret_cast<float2*>(&out[(size_t)(row0 + ra) * HD + col]) =
                    make_float2(acc[o][mf][nf][0] + b0v, acc[o][mf][nf][1] + b1v);
                *reinterpret_cast<float2*>(&out[(size_t)(row0 + rb) * HD + col]) =
                    make_float2(acc[o][mf][nf][2] + b0v, acc[o][mf][nf][3] + b1v);
            }
        }
    }
}

// ---------------------------------------------------------------------------
// Kernel 2: split-K causal flash attention chunk (tf32 mma), 512 threads.
// (unchanged from round 8 — measured ~85us incl. combine)
// ---------------------------------------------------------------------------
__global__ __launch_bounds__(ATHREADS) void attn_chunk_kernel()
{
    extern __shared__ float smbuf[];
    float* sQ = smbuf;                 // [64][QS]
    float* sK = sQ + 64 * QS;
    float* sV = sK + 64 * QS;          // [64][VS]
    float* sP = sV + 64 * VS;          // [64][PS]
    float* sM = sP + 64 * PS;
    float* sL = sM + 64;
    float* sC = sL + 64;

    const int tid  = threadIdx.x;
    const int lane = tid & 31;
    const int wid  = tid >> 5;         // 0..15
    const int l4   = lane & 3;
    const int g8   = lane >> 2;

    // decode chunk id -> (b, qt, ck)
    const int cid = blockIdx.x;
    const int b   = cid / CH_PER_BATCH;
    const int f   = cid % CH_PER_BATCH;
    int qt, ck;
    if (f < 8)        { qt = f;                 ck = 0; }
    else if (f < 24)  { qt = 8  + (f - 8)  / 2; ck = (f - 8)  % 2; }
    else if (f < 48)  { qt = 16 + (f - 24) / 3; ck = (f - 24) % 3; }
    else              { qt = 24 + (f - 48) / 4; ck = (f - 48) % 4; }

    const int kt_begin = ck * CHTILES;
    int kt_end = kt_begin + CHTILES;
    if (kt_end > qt + 1) kt_end = qt + 1;

    const int q0 = qt * BM;
    const float* Q = g_q + (size_t)b * SEQ * HD;
    const float* K = g_k + (size_t)b * SEQ * HD;
    const float* V = g_v + (size_t)b * SEQ * HD;

    const float scale = 0.08838834764831845f;

    // load Q tile (tf32): 2048 float4 over 512 threads
#pragma unroll
    for (int s = 0; s < 4; s++) {
        int ff = tid + s * ATHREADS;
        int r  = ff >> 5;
        int k0 = (ff & 31) * 4;
        float4 v4 = *reinterpret_cast<const float4*>(&Q[(size_t)(q0 + r) * HD + k0]);
        float4 t4;
        t4.x = __uint_as_float(tf32_bits(v4.x));
        t4.y = __uint_as_float(tf32_bits(v4.y));
        t4.z = __uint_as_float(tf32_bits(v4.z));
        t4.w = __uint_as_float(tf32_bits(v4.w));
        *reinterpret_cast<float4*>(&sQ[r * QS + k0]) = t4;
    }
    if (tid < 64) { sM[tid] = -1e30f; sL[tid] = 0.0f; }

    // QK warp mapping: 4(m) x 4(n), warp tile 16x16
    const int m0 = (wid >> 2) * 16;
    const int n0 = (wid & 3) * 16;

    // PV warp mapping: 8 d-tiles x 2 q-halves
    const int d0    = (wid >> 1) * 16;   // d tile base
    const int nbase = (wid & 1) * 4;     // n-frag base (q-rows nbase*8 .. +32)

    // Softmax mapping: 8 threads per row, 8 cols each (within-warp octet)
    const int srow = tid >> 3;           // 0..63
    const int sl8  = tid & 7;
    const int sc0  = sl8 * 8;

    float cO[4][4];
#pragma unroll
    for (int i = 0; i < 4; i++)
#pragma unroll
        for (int j = 0; j < 4; j++) cO[i][j] = 0.0f;

    for (int kt = kt_begin; kt < kt_end; kt++) {
        const int k0g = kt * BN;
        __syncthreads();

        // fill K and V tiles (tf32): 2048 float4 each over 512 threads
#pragma unroll
        for (int s = 0; s < 4; s++) {
            int ff = tid + s * ATHREADS;
            int r  = ff >> 5;
            int c  = (ff & 31) * 4;
            float4 kv = *reinterpret_cast<const float4*>(&K[(size_t)(k0g + r) * HD + c]);
            float4 tk;
            tk.x = __uint_as_float(tf32_bits(kv.x));
            tk.y = __uint_as_float(tf32_bits(kv.y));
            tk.z = __uint_as_float(tf32_bits(kv.z));
            tk.w = __uint_as_float(tf32_bits(kv.w));
            *reinterpret_cast<float4*>(&sK[r * QS + c]) = tk;

            float4 vv = *reinterpret_cast<const float4*>(&V[(size_t)(k0g + r) * HD + c]);
            float4 tv;
            tv.x = __uint_as_float(tf32_bits(vv.x));
            tv.y = __uint_as_float(tf32_bits(vv.y));
            tv.z = __uint_as_float(tf32_bits(vv.z));
            tv.w = __uint_as_float(tf32_bits(vv.w));
            *reinterpret_cast<float4*>(&sV[r * VS + c]) = tv;
        }
        __syncthreads();

        // S = Q K^T (warp tile 16x16 -> 2 n-frags)
        float cS[2][4];
#pragma unroll
        for (int i = 0; i < 2; i++)
#pragma unroll
            for (int j = 0; j < 4; j++) cS[i][j] = 0.0f;

#pragma unroll
        for (int kk = 0; kk < HD; kk += 8) {
            const float* aq = &sQ[(m0 + g8) * QS + kk + l4];
            uint32_t a0 = __float_as_uint(aq[0]);
            uint32_t a1 = __float_as_uint(aq[8 * QS]);
            uint32_t a2 = __float_as_uint(aq[4]);
            uint32_t a3 = __float_as_uint(aq[8 * QS + 4]);
#pragma unroll
            for (int nf = 0; nf < 2; nf++) {
                const float* bk = &sK[(n0 + nf * 8 + g8) * QS + kk + l4];
                uint32_t b0 = __float_as_uint(bk[0]);
                uint32_t b1 = __float_as_uint(bk[4]);
                mma_tf32(cS[nf], a0, a1, a2, a3, b0, b1);
            }
        }

        // scale + causal mask -> sP
        {
            const bool diag = (kt == qt);
            const int row_a = m0 + g8;
            const int row_b = row_a + 8;
#pragma unroll
            for (int nf = 0; nf < 2; nf++) {
                int col = n0 + nf * 8 + 2 * l4;
                float v0 = cS[nf][0] * scale;
                float v1 = cS[nf][1] * scale;
                float v2 = cS[nf][2] * scale;
                float v3 = cS[nf][3] * scale;
                if (diag) {
                    if (col     > row_a) v0 = -1e30f;
                    if (col + 1 > row_a) v1 = -1e30f;
                    if (col     > row_b) v2 = -1e30f;
                    if (col + 1 > row_b) v3 = -1e30f;
                }
                *reinterpret_cast<float2*>(&sP[row_a * PS + col]) = make_float2(v0, v1);
                *reinterpret_cast<float2*>(&sP[row_b * PS + col]) = make_float2(v2, v3);
            }
        }
        __syncthreads();

        // online softmax: 8 threads/row, octet shfl reductions
        {
            float* prow = &sP[srow * PS + sc0];
            float mt = -1e30f;
#pragma unroll
            for (int j = 0; j < 8; j++) mt = fmaxf(mt, prow[j]);
            mt = fmaxf(mt, __shfl_xor_sync(0xFFFFFFFFu, mt, 1));
            mt = fmaxf(mt, __shfl_xor_sync(0xFFFFFFFFu, mt, 2));
            mt = fmaxf(mt, __shfl_xor_sync(0xFFFFFFFFu, mt, 4));

            float m0v  = sM[srow];
            float mnew = fmaxf(m0v, mt);

            float sum = 0.0f;
#pragma unroll
            for (int j = 0; j < 8; j++) {
                float p = __expf(prow[j] - mnew);
                float pr = __uint_as_float(tf32_bits(p));
                prow[j] = pr;
                sum += pr;
            }
            sum += __shfl_xor_sync(0xFFFFFFFFu, sum, 1);
            sum += __shfl_xor_sync(0xFFFFFFFFu, sum, 2);
            sum += __shfl_xor_sync(0xFFFFFFFFu, sum, 4);

            if (sl8 == 0) {
                float corr = __expf(m0v - mnew);
                sL[srow] = sL[srow] * corr + sum;
                sM[srow] = mnew;
                sC[srow] = corr;
            }
        }
        __syncthreads();

        // rescale O^T accumulators by per-q-row corr
#pragma unroll
        for (int nf = 0; nf < 4; nf++) {
            int col = (nbase + nf) * 8 + 2 * l4;
            float cr0 = sC[col];
            float cr1 = sC[col + 1];
            cO[nf][0] *= cr0;
            cO[nf][1] *= cr1;
            cO[nf][2] *= cr0;
            cO[nf][3] *= cr1;
        }

        // O^T += V^T @ P^T  (A = V^T from sV, B = P^T from sP)
#pragma unroll
        for (int kk = 0; kk < BN; kk += 8) {
            const float* av = &sV[(kk + l4) * VS + d0 + g8];
            uint32_t a0 = __float_as_uint(av[0]);
            uint32_t a1 = __float_as_uint(av[8]);
            uint32_t a2 = __float_as_uint(av[4 * VS]);
            uint32_t a3 = __float_as_uint(av[4 * VS + 8]);
#pragma unroll
            for (int nf = 0; nf < 4; nf++) {
                const float* bp = &sP[((nbase + nf) * 8 + g8) * PS + kk + l4];
                uint32_t b0 = __float_as_uint(bp[0]);
                uint32_t b1 = __float_as_uint(bp[4]);
                mma_tf32(cO[nf], a0, a1, a2, a3, b0, b1);
            }
        }
    }

    // epilogue: write unnormalized partials + (m, l)
    __syncthreads();
    float* PO = g_po + (size_t)cid * BM * HD;
#pragma unroll
    for (int nf = 0; nf < 4; nf++) {
        int col0 = (nbase + nf) * 8 + 2 * l4;
        int d = d0 + g8;
        PO[(col0    ) * HD + d]     = cO[nf][0];
        PO[(col0 + 1) * HD + d]     = cO[nf][1];
        PO[(col0    ) * HD + d + 8] = cO[nf][2];
        PO[(col0 + 1) * HD + d + 8] = cO[nf][3];
    }
    if (tid < 64) {
        g_pm[cid * BM + tid] = sM[tid];
        g_pl[cid * BM + tid] = sL[tid];
    }
}

// ---------------------------------------------------------------------------
// Kernel 3: combine partial chunks.  grid (32 qt, 4 b), 256 threads.
// ---------------------------------------------------------------------------
__global__ __launch_bounds__(NTHREADS) void attn_combine_kernel(float* __restrict__ out)
{
    __shared__ float sW[4][64];
    __shared__ float sLinv[64];

    const int tid = threadIdx.x;
    const int qt  = blockIdx.x;
    const int b   = blockIdx.y;
    const int q0  = qt * BM;

    // chunk range for this (b, qt)
    int start;
    if (qt < 8)       start = qt;
    else if (qt < 16) start = 8  + 2 * (qt - 8);
    else if (qt < 24) start = 24 + 3 * (qt - 16);
    else              start = 48 + 4 * (qt - 24);
    const int nc   = qt / 8 + 1;
    const int base = b * CH_PER_BATCH + start;

    // per-row weights
    if (tid < 64) {
        const int r = tid;
        float M = -1e30f;
        float mv[4];
        for (int c = 0; c < nc; c++) {
            mv[c] = g_pm[(base + c) * BM + r];
            M = fmaxf(M, mv[c]);
        }
        float L = 0.0f;
        for (int c = 0; c < nc; c++) {
            float wc = __expf(mv[c] - M);
            sW[c][r] = wc;
            L += wc * g_pl[(base + c) * BM + r];
        }
        sLinv[r] = 1.0f / L;
    }
    __syncthreads();

    float* O = out + ((size_t)b * SEQ + q0) * HD;
#pragma unroll 4
    for (int s = 0; s < 32; s++) {
        int e = tid + s * NTHREADS;   // 0..8191
        int r = e >> 7;
        float acc = 0.0f;
        for (int c = 0; c < nc; c++)
            acc += sW[c][r] * g_po[(size_t)(base + c) * BM * HD + e];
        O[e] = acc * sLinv[r];
    }
}

// ---------------------------------------------------------------------------
extern "C" void kernel_launch(void* const* d_in, const int* in_sizes, int n_in,
                              void* d_out, int out_size)
{
    const float* x  = (const float*)d_in[0];
    const float* wq = (const float*)d_in[1];
    const float* bq = (const float*)d_in[2];
    const float* wk = (const float*)d_in[3];
    const float* bk = (const float*)d_in[4];
    const float* wv = (const float*)d_in[5];
    const float* bv = (const float*)d_in[6];
    float* out = (float*)d_out;

    // Fused QKV projection: 128 CTAs (one per 64-row tile), 512 threads
    const int proj_smem = (64 * XS + 3 * 32 * WS2) * sizeof(float);  // ~61.4 KB
    cudaFuncSetAttribute(qkv_proj_kernel, cudaFuncAttributeMaxDynamicSharedMemorySize,
                         proj_smem);
    qkv_proj_kernel<<<128, PTHREADS, proj_smem>>>(x, wq, bq, wk, bk, wv, bv);

    const int smem_bytes =
        (64 * QS * 2 + 64 * VS + 64 * PS + 3 * 64) * sizeof(float);
    cudaFuncSetAttribute(attn_chunk_kernel, cudaFuncAttributeMaxDynamicSharedMemorySize,
                         smem_bytes);
    attn_chunk_kernel<<<CHUNKS_TOTAL, ATHREADS, smem_bytes>>>();

    attn_combine_kernel<<<dim3(32, BATCH), NTHREADS>>>(out);
}